// round 1
// baseline (speedup 1.0000x reference)
#include <cuda_runtime.h>
#include <math.h>

// Problem constants
#define B_ 8
#define C_ 512
#define N_ 2048
#define P_ 256

// ---------------- scratch (static device globals; no allocation) ----------------
__device__ float d_theta[B_ * N_ * P_];          // [B][N][P] rows = Q
__device__ float d_phi  [B_ * N_ * P_];          // [B][N][P] rows = K
__device__ float d_g    [B_ * N_ * P_];          // [B][N][P] rows = V
__device__ float d_S    [(size_t)B_ * N_ * N_];  // [B][N][N] scores / probs
__device__ float d_O    [B_ * N_ * P_];          // [B][N][P] attention out rows
__device__ float d_zp   [(size_t)C_ * B_ * N_];  // [C][B*N]  z in channel-major layout
__device__ float d_scale[C_];
__device__ float d_shift[C_];

// ---------------- generic fp32 tiled GEMM ----------------
// C[i, j] = sum_k A(k, i) * Bm(k, j)
//   AKM  ? A(k,i) = A[k*lda + i]  (k-major, contiguous i)
//        : A(k,i) = A[i*lda + k]  (row-major, contiguous k)
//   BKM  ? B(k,j) = B[k*ldb + j]
//        : B(k,j) = B[j*ldb + k]
// Tiles: 128x128x16, 256 threads, 8x8 per thread. All dims divisible by tiles.
template <bool AKM, bool BKM>
__launch_bounds__(256, 2)
__global__ void gemm_kernel(const float* __restrict__ A,
                            const float* __restrict__ Bm,
                            float* __restrict__ Cm,
                            int K, int lda, int ldb, int ldc,
                            size_t sA, size_t sB, size_t sC)
{
    __shared__ float As[16][132];
    __shared__ float Bs[16][132];

    const int tid = threadIdx.x;
    const int bz = blockIdx.z;
    A  += (size_t)bz * sA;
    Bm += (size_t)bz * sB;
    Cm += (size_t)bz * sC;

    const int m0 = blockIdx.y * 128;
    const int n0 = blockIdx.x * 128;
    const int tx = tid & 15;   // 0..15
    const int ty = tid >> 4;   // 0..15

    float acc[8][8];
#pragma unroll
    for (int i = 0; i < 8; i++)
#pragma unroll
        for (int j = 0; j < 8; j++) acc[i][j] = 0.f;

    for (int k0 = 0; k0 < K; k0 += 16) {
        // ---- load A tile -> As[k][m] ----
        if (AKM) {
#pragma unroll
            for (int r = 0; r < 2; r++) {
                int lin = tid + r * 256;        // 0..511
                int k   = lin >> 5;             // 0..15
                int m4  = (lin & 31) << 2;      // 0..124
                float4 v = *(const float4*)&A[(size_t)(k0 + k) * lda + m0 + m4];
                *(float4*)&As[k][m4] = v;
            }
        } else {
#pragma unroll
            for (int r = 0; r < 2; r++) {
                int lin = tid + r * 256;
                int m   = lin >> 2;             // 0..127
                int k4  = (lin & 3) << 2;       // 0,4,8,12
                float4 v = *(const float4*)&A[(size_t)(m0 + m) * lda + k0 + k4];
                As[k4 + 0][m] = v.x;
                As[k4 + 1][m] = v.y;
                As[k4 + 2][m] = v.z;
                As[k4 + 3][m] = v.w;
            }
        }
        // ---- load B tile -> Bs[k][j] ----
        if (BKM) {
#pragma unroll
            for (int r = 0; r < 2; r++) {
                int lin = tid + r * 256;
                int k   = lin >> 5;
                int j4  = (lin & 31) << 2;
                float4 v = *(const float4*)&Bm[(size_t)(k0 + k) * ldb + n0 + j4];
                *(float4*)&Bs[k][j4] = v;
            }
        } else {
#pragma unroll
            for (int r = 0; r < 2; r++) {
                int lin = tid + r * 256;
                int j   = lin >> 2;
                int k4  = (lin & 3) << 2;
                float4 v = *(const float4*)&Bm[(size_t)(n0 + j) * ldb + k0 + k4];
                Bs[k4 + 0][j] = v.x;
                Bs[k4 + 1][j] = v.y;
                Bs[k4 + 2][j] = v.z;
                Bs[k4 + 3][j] = v.w;
            }
        }
        __syncthreads();

#pragma unroll
        for (int kk = 0; kk < 16; kk++) {
            float a[8], b[8];
            *(float4*)&a[0] = *(const float4*)&As[kk][ty * 8];
            *(float4*)&a[4] = *(const float4*)&As[kk][ty * 8 + 4];
            *(float4*)&b[0] = *(const float4*)&Bs[kk][tx * 8];
            *(float4*)&b[4] = *(const float4*)&Bs[kk][tx * 8 + 4];
#pragma unroll
            for (int i = 0; i < 8; i++)
#pragma unroll
                for (int j = 0; j < 8; j++)
                    acc[i][j] += a[i] * b[j];
        }
        __syncthreads();
    }

#pragma unroll
    for (int i = 0; i < 8; i++) {
        int row = m0 + ty * 8 + i;
        float* cp = Cm + (size_t)row * ldc + n0 + tx * 8;
        *(float4*)cp       = make_float4(acc[i][0], acc[i][1], acc[i][2], acc[i][3]);
        *(float4*)(cp + 4) = make_float4(acc[i][4], acc[i][5], acc[i][6], acc[i][7]);
    }
}

// ---------------- row softmax over N_=2048, one block per row ----------------
__global__ void softmax_kernel(float* __restrict__ S)
{
    __shared__ float red[256];
    float* row = S + (size_t)blockIdx.x * N_;
    const int tid = threadIdx.x;

    float4 v0 = ((float4*)row)[tid];
    float4 v1 = ((float4*)row)[tid + 256];

    float m = fmaxf(fmaxf(fmaxf(v0.x, v0.y), fmaxf(v0.z, v0.w)),
                    fmaxf(fmaxf(v1.x, v1.y), fmaxf(v1.z, v1.w)));
    red[tid] = m;
    __syncthreads();
    for (int s = 128; s > 0; s >>= 1) {
        if (tid < s) red[tid] = fmaxf(red[tid], red[tid + s]);
        __syncthreads();
    }
    const float rowmax = red[0];
    __syncthreads();

    v0.x = expf(v0.x - rowmax); v0.y = expf(v0.y - rowmax);
    v0.z = expf(v0.z - rowmax); v0.w = expf(v0.w - rowmax);
    v1.x = expf(v1.x - rowmax); v1.y = expf(v1.y - rowmax);
    v1.z = expf(v1.z - rowmax); v1.w = expf(v1.w - rowmax);

    float sum = (v0.x + v0.y + v0.z + v0.w) + (v1.x + v1.y + v1.z + v1.w);
    red[tid] = sum;
    __syncthreads();
    for (int s = 128; s > 0; s >>= 1) {
        if (tid < s) red[tid] += red[tid + s];
        __syncthreads();
    }
    const float inv = 1.0f / red[0];

    v0.x *= inv; v0.y *= inv; v0.z *= inv; v0.w *= inv;
    v1.x *= inv; v1.y *= inv; v1.z *= inv; v1.w *= inv;
    ((float4*)row)[tid]       = v0;
    ((float4*)row)[tid + 256] = v1;
}

// ---------------- BN batch statistics per channel (z stored [C][B*N]) ----------------
__global__ void bn_stats_kernel(const float* __restrict__ zp,
                                const float* __restrict__ gamma,
                                const float* __restrict__ beta,
                                float* __restrict__ scale,
                                float* __restrict__ shift)
{
    __shared__ double rs[256];
    __shared__ double rs2[256];
    const int c = blockIdx.x;
    const int tid = threadIdx.x;
    const float* row = zp + (size_t)c * (B_ * N_);

    double s = 0.0, s2 = 0.0;
    const int n4 = (B_ * N_) / 4;  // 4096
    for (int i = tid; i < n4; i += 256) {
        float4 v = ((const float4*)row)[i];
        s  += (double)v.x + (double)v.y + (double)v.z + (double)v.w;
        s2 += (double)v.x * v.x + (double)v.y * v.y +
              (double)v.z * v.z + (double)v.w * v.w;
    }
    rs[tid] = s; rs2[tid] = s2;
    __syncthreads();
    for (int st = 128; st > 0; st >>= 1) {
        if (tid < st) { rs[tid] += rs[tid + st]; rs2[tid] += rs2[tid + st]; }
        __syncthreads();
    }
    if (tid == 0) {
        const double M = (double)(B_ * N_);
        double mean = rs[0] / M;
        double var  = rs2[0] / M - mean * mean;
        double inv  = 1.0 / sqrt(var + 1e-5);
        double sc   = (double)gamma[c] * inv;
        scale[c] = (float)sc;
        shift[c] = (float)((double)beta[c] - mean * sc);
    }
}

// ---------------- out[b,c,n] = zp[c][b*N+n]*scale[c] + shift[c] + x[b,c,n] ----------------
__global__ void finalize_kernel(const float* __restrict__ zp,
                                const float* __restrict__ x,
                                const float* __restrict__ scale,
                                const float* __restrict__ shift,
                                float* __restrict__ out)
{
    const size_t idx4 = (size_t)blockIdx.x * blockDim.x + threadIdx.x;
    const size_t total4 = (size_t)B_ * C_ * N_ / 4;
    if (idx4 >= total4) return;
    const int nq  = N_ / 4;              // 512 float4 per n-row
    int n4 = (int)(idx4 % nq);
    int c  = (int)((idx4 / nq) % C_);
    int b  = (int)(idx4 / ((size_t)nq * C_));

    float4 z = ((const float4*)zp)[(size_t)c * (B_ * N_ / 4) + (size_t)b * nq + n4];
    float4 xv = ((const float4*)x)[idx4];
    const float sc = scale[c], sh = shift[c];
    float4 o;
    o.x = z.x * sc + sh + xv.x;
    o.y = z.y * sc + sh + xv.y;
    o.z = z.z * sc + sh + xv.z;
    o.w = z.w * sc + sh + xv.w;
    ((float4*)out)[idx4] = o;
}

// ---------------- launch ----------------
static float* sym_addr(const void* sym)
{
    void* p = nullptr;
    cudaGetSymbolAddress(&p, sym);
    return (float*)p;
}

extern "C" void kernel_launch(void* const* d_in, const int* in_sizes, int n_in,
                              void* d_out, int out_size)
{
    const float* x     = (const float*)d_in[0];
    const float* Wg    = (const float*)d_in[1];
    const float* Wth   = (const float*)d_in[2];
    const float* Wph   = (const float*)d_in[3];
    const float* Wz    = (const float*)d_in[4];
    const float* gamma = (const float*)d_in[5];
    const float* beta  = (const float*)d_in[6];
    float* out = (float*)d_out;

    float* theta = sym_addr(d_theta);
    float* phi   = sym_addr(d_phi);
    float* g     = sym_addr(d_g);
    float* S     = sym_addr(d_S);
    float* O     = sym_addr(d_O);
    float* zp    = sym_addr(d_zp);
    float* scale = sym_addr(d_scale);
    float* shift = sym_addr(d_shift);

    // 1) projections: out[n,p] = sum_c x[b,c,n] * W[p,c]
    //    A = x (k-major: A[k*lda+m], lda=N), B = W (B[j*ldb+k], ldb=C)
    {
        dim3 grid(P_ / 128, N_ / 128, B_);
        gemm_kernel<true, false><<<grid, 256>>>(x, Wth, theta,
            C_, N_, C_, P_, (size_t)C_ * N_, 0, (size_t)N_ * P_);
        gemm_kernel<true, false><<<grid, 256>>>(x, Wph, phi,
            C_, N_, C_, P_, (size_t)C_ * N_, 0, (size_t)N_ * P_);
        gemm_kernel<true, false><<<grid, 256>>>(x, Wg, g,
            C_, N_, C_, P_, (size_t)C_ * N_, 0, (size_t)N_ * P_);
    }

    // 2) scores: S[n,m] = sum_p theta[n,p] * phi[m,p]   (NT)
    {
        dim3 grid(N_ / 128, N_ / 128, B_);
        gemm_kernel<false, false><<<grid, 256>>>(theta, phi, S,
            P_, P_, P_, N_, (size_t)N_ * P_, (size_t)N_ * P_, (size_t)N_ * N_);
    }

    // 3) row softmax over S
    softmax_kernel<<<B_ * N_, 256>>>(S);

    // 4) PV: O[n,p] = sum_m S[n,m] * g[m,p]   (NN)
    {
        dim3 grid(P_ / 128, N_ / 128, B_);
        gemm_kernel<false, true><<<grid, 256>>>(S, g, O,
            N_, N_, P_, P_, (size_t)N_ * N_, (size_t)N_ * P_, (size_t)N_ * P_);
    }

    // 5) z: zp[c, b*N+n] = sum_p Wz[c,p] * O[(b*N+n), p]   (NT, batch folded into columns)
    {
        dim3 grid((B_ * N_) / 128, C_ / 128, 1);
        gemm_kernel<false, false><<<grid, 256>>>(Wz, O, zp,
            P_, P_, P_, B_ * N_, 0, 0, 0);
    }

    // 6) BN statistics per channel
    bn_stats_kernel<<<C_, 256>>>(zp, gamma, beta, scale, shift);

    // 7) normalize + affine + residual
    {
        const int total4 = B_ * C_ * N_ / 4;
        finalize_kernel<<<(total4 + 255) / 256, 256>>>(zp, x, scale, shift, out);
    }
}

// round 2
// speedup vs baseline: 1.0413x; 1.0413x over previous
#include <cuda_runtime.h>
#include <math.h>

// Problem constants
#define B_ 8
#define C_ 512
#define N_ 2048
#define P_ 256

// ---------------- scratch (static device globals; no allocation) ----------------
__device__ float d_theta[B_ * N_ * P_];          // [B][N][P] rows = Q
__device__ float d_phi  [B_ * N_ * P_];          // [B][N][P] rows = K
__device__ float d_g    [B_ * N_ * P_];          // [B][N][P] rows = V
__device__ float d_S    [(size_t)B_ * N_ * N_];  // [B][N][N] scores / probs
__device__ float d_O    [B_ * N_ * P_];          // [B][N][P] attention out rows
__device__ float d_zp   [(size_t)C_ * B_ * N_];  // [C][B*N]  z in channel-major layout
__device__ float d_scale[C_];
__device__ float d_shift[C_];

// ---------------- pipelined fp32 tiled GEMM ----------------
// C[i, j] = sum_k A(k, i) * Bm(k, j)
//   AKM  ? A(k,i) = A[k*lda + i]  (k-major, contiguous i)
//        : A(k,i) = A[i*lda + k]  (row-major, contiguous k)
//   BKM  ? B(k,j) = B[k*ldb + j]
//        : B(k,j) = B[j*ldb + k]
// Tiles: 128x128x16, 256 threads, 8x8 per thread.
// Double-buffered smem + global->reg prefetch: one barrier per k-tile.
template <bool AKM, bool BKM>
__launch_bounds__(256, 2)
__global__ void gemm_kernel(const float* __restrict__ A,
                            const float* __restrict__ Bm,
                            float* __restrict__ Cm,
                            int K, int lda, int ldb, int ldc,
                            size_t sA, size_t sB, size_t sC)
{
    __shared__ float As[2][16][132];
    __shared__ float Bs[2][16][132];

    const int tid = threadIdx.x;
    const int bz = blockIdx.z;
    A  += (size_t)bz * sA;
    Bm += (size_t)bz * sB;
    Cm += (size_t)bz * sC;

    const int m0 = blockIdx.y * 128;
    const int n0 = blockIdx.x * 128;
    const int tx = tid & 15;   // 0..15
    const int ty = tid >> 4;   // 0..15

    float acc[8][8];
#pragma unroll
    for (int i = 0; i < 8; i++)
#pragma unroll
        for (int j = 0; j < 8; j++) acc[i][j] = 0.f;

    float4 pa[2], pb[2];

    // ---- global load of tile starting at k0 into registers ----
    auto loadA = [&](int k0) {
#pragma unroll
        for (int r = 0; r < 2; r++) {
            int lin = tid + r * 256;
            if (AKM) {
                int k  = lin >> 5;             // 0..15
                int m4 = (lin & 31) << 2;      // 0..124
                pa[r] = *(const float4*)&A[(size_t)(k0 + k) * lda + m0 + m4];
            } else {
                int m  = lin >> 2;             // 0..127
                int k4 = (lin & 3) << 2;       // 0,4,8,12
                pa[r] = *(const float4*)&A[(size_t)(m0 + m) * lda + k0 + k4];
            }
        }
    };
    auto loadB = [&](int k0) {
#pragma unroll
        for (int r = 0; r < 2; r++) {
            int lin = tid + r * 256;
            if (BKM) {
                int k  = lin >> 5;
                int j4 = (lin & 31) << 2;
                pb[r] = *(const float4*)&Bm[(size_t)(k0 + k) * ldb + n0 + j4];
            } else {
                int j  = lin >> 2;
                int k4 = (lin & 3) << 2;
                pb[r] = *(const float4*)&Bm[(size_t)(n0 + j) * ldb + k0 + k4];
            }
        }
    };
    auto storeAB = [&](int buf) {
#pragma unroll
        for (int r = 0; r < 2; r++) {
            int lin = tid + r * 256;
            if (AKM) {
                int k  = lin >> 5;
                int m4 = (lin & 31) << 2;
                *(float4*)&As[buf][k][m4] = pa[r];
            } else {
                int m  = lin >> 2;
                int k4 = (lin & 3) << 2;
                As[buf][k4 + 0][m] = pa[r].x;
                As[buf][k4 + 1][m] = pa[r].y;
                As[buf][k4 + 2][m] = pa[r].z;
                As[buf][k4 + 3][m] = pa[r].w;
            }
            if (BKM) {
                int k  = lin >> 5;
                int j4 = (lin & 31) << 2;
                *(float4*)&Bs[buf][k][j4] = pb[r];
            } else {
                int j  = lin >> 2;
                int k4 = (lin & 3) << 2;
                Bs[buf][k4 + 0][j] = pb[r].x;
                Bs[buf][k4 + 1][j] = pb[r].y;
                Bs[buf][k4 + 2][j] = pb[r].z;
                Bs[buf][k4 + 3][j] = pb[r].w;
            }
        }
    };

    // prologue: tile 0
    loadA(0); loadB(0);
    storeAB(0);
    __syncthreads();

    int buf = 0;
    for (int k0 = 0; k0 < K; k0 += 16) {
        const bool more = (k0 + 16 < K);
        if (more) { loadA(k0 + 16); loadB(k0 + 16); }

#pragma unroll
        for (int kk = 0; kk < 16; kk++) {
            float a[8], b[8];
            *(float4*)&a[0] = *(const float4*)&As[buf][kk][ty * 8];
            *(float4*)&a[4] = *(const float4*)&As[buf][kk][ty * 8 + 4];
            *(float4*)&b[0] = *(const float4*)&Bs[buf][kk][tx * 8];
            *(float4*)&b[4] = *(const float4*)&Bs[buf][kk][tx * 8 + 4];
#pragma unroll
            for (int i = 0; i < 8; i++)
#pragma unroll
                for (int j = 0; j < 8; j++)
                    acc[i][j] += a[i] * b[j];
        }

        if (more) {
            storeAB(buf ^ 1);
            __syncthreads();
            buf ^= 1;
        }
    }

#pragma unroll
    for (int i = 0; i < 8; i++) {
        int row = m0 + ty * 8 + i;
        float* cp = Cm + (size_t)row * ldc + n0 + tx * 8;
        *(float4*)cp       = make_float4(acc[i][0], acc[i][1], acc[i][2], acc[i][3]);
        *(float4*)(cp + 4) = make_float4(acc[i][4], acc[i][5], acc[i][6], acc[i][7]);
    }
}

// ---------------- row softmax over N_=2048, one block per row ----------------
__global__ void softmax_kernel(float* __restrict__ S)
{
    __shared__ float red[256];
    float* row = S + (size_t)blockIdx.x * N_;
    const int tid = threadIdx.x;

    float4 v0 = ((float4*)row)[tid];
    float4 v1 = ((float4*)row)[tid + 256];

    float m = fmaxf(fmaxf(fmaxf(v0.x, v0.y), fmaxf(v0.z, v0.w)),
                    fmaxf(fmaxf(v1.x, v1.y), fmaxf(v1.z, v1.w)));
    red[tid] = m;
    __syncthreads();
    for (int s = 128; s > 0; s >>= 1) {
        if (tid < s) red[tid] = fmaxf(red[tid], red[tid + s]);
        __syncthreads();
    }
    const float rowmax = red[0];
    __syncthreads();

    v0.x = expf(v0.x - rowmax); v0.y = expf(v0.y - rowmax);
    v0.z = expf(v0.z - rowmax); v0.w = expf(v0.w - rowmax);
    v1.x = expf(v1.x - rowmax); v1.y = expf(v1.y - rowmax);
    v1.z = expf(v1.z - rowmax); v1.w = expf(v1.w - rowmax);

    float sum = (v0.x + v0.y + v0.z + v0.w) + (v1.x + v1.y + v1.z + v1.w);
    red[tid] = sum;
    __syncthreads();
    for (int s = 128; s > 0; s >>= 1) {
        if (tid < s) red[tid] += red[tid + s];
        __syncthreads();
    }
    const float inv = 1.0f / red[0];

    v0.x *= inv; v0.y *= inv; v0.z *= inv; v0.w *= inv;
    v1.x *= inv; v1.y *= inv; v1.z *= inv; v1.w *= inv;
    ((float4*)row)[tid]       = v0;
    ((float4*)row)[tid + 256] = v1;
}

// ---------------- BN batch statistics per channel (z stored [C][B*N]) ----------------
__global__ void bn_stats_kernel(const float* __restrict__ zp,
                                const float* __restrict__ gamma,
                                const float* __restrict__ beta,
                                float* __restrict__ scale,
                                float* __restrict__ shift)
{
    __shared__ double rs[256];
    __shared__ double rs2[256];
    const int c = blockIdx.x;
    const int tid = threadIdx.x;
    const float* row = zp + (size_t)c * (B_ * N_);

    double s = 0.0, s2 = 0.0;
    const int n4 = (B_ * N_) / 4;  // 4096
    for (int i = tid; i < n4; i += 256) {
        float4 v = ((const float4*)row)[i];
        s  += (double)v.x + (double)v.y + (double)v.z + (double)v.w;
        s2 += (double)v.x * v.x + (double)v.y * v.y +
              (double)v.z * v.z + (double)v.w * v.w;
    }
    rs[tid] = s; rs2[tid] = s2;
    __syncthreads();
    for (int st = 128; st > 0; st >>= 1) {
        if (tid < st) { rs[tid] += rs[tid + st]; rs2[tid] += rs2[tid + st]; }
        __syncthreads();
    }
    if (tid == 0) {
        const double M = (double)(B_ * N_);
        double mean = rs[0] / M;
        double var  = rs2[0] / M - mean * mean;
        double inv  = 1.0 / sqrt(var + 1e-5);
        double sc   = (double)gamma[c] * inv;
        scale[c] = (float)sc;
        shift[c] = (float)((double)beta[c] - mean * sc);
    }
}

// ---------------- out[b,c,n] = zp[c][b*N+n]*scale[c] + shift[c] + x[b,c,n] ----------------
__global__ void finalize_kernel(const float* __restrict__ zp,
                                const float* __restrict__ x,
                                const float* __restrict__ scale,
                                const float* __restrict__ shift,
                                float* __restrict__ out)
{
    const size_t idx4 = (size_t)blockIdx.x * blockDim.x + threadIdx.x;
    const size_t total4 = (size_t)B_ * C_ * N_ / 4;
    if (idx4 >= total4) return;
    const int nq  = N_ / 4;              // 512 float4 per n-row
    int n4 = (int)(idx4 % nq);
    int c  = (int)((idx4 / nq) % C_);
    int b  = (int)(idx4 / ((size_t)nq * C_));

    float4 z = ((const float4*)zp)[(size_t)c * (B_ * N_ / 4) + (size_t)b * nq + n4];
    float4 xv = ((const float4*)x)[idx4];
    const float sc = scale[c], sh = shift[c];
    float4 o;
    o.x = z.x * sc + sh + xv.x;
    o.y = z.y * sc + sh + xv.y;
    o.z = z.z * sc + sh + xv.z;
    o.w = z.w * sc + sh + xv.w;
    ((float4*)out)[idx4] = o;
}

// ---------------- launch ----------------
static float* sym_addr(const void* sym)
{
    void* p = nullptr;
    cudaGetSymbolAddress(&p, sym);
    return (float*)p;
}

extern "C" void kernel_launch(void* const* d_in, const int* in_sizes, int n_in,
                              void* d_out, int out_size)
{
    const float* x     = (const float*)d_in[0];
    const float* Wg    = (const float*)d_in[1];
    const float* Wth   = (const float*)d_in[2];
    const float* Wph   = (const float*)d_in[3];
    const float* Wz    = (const float*)d_in[4];
    const float* gamma = (const float*)d_in[5];
    const float* beta  = (const float*)d_in[6];
    float* out = (float*)d_out;

    float* theta = sym_addr(d_theta);
    float* phi   = sym_addr(d_phi);
    float* g     = sym_addr(d_g);
    float* S     = sym_addr(d_S);
    float* O     = sym_addr(d_O);
    float* zp    = sym_addr(d_zp);
    float* scale = sym_addr(d_scale);
    float* shift = sym_addr(d_shift);

    // 1) projections: out[n,p] = sum_c x[b,c,n] * W[p,c]
    {
        dim3 grid(P_ / 128, N_ / 128, B_);
        gemm_kernel<true, false><<<grid, 256>>>(x, Wth, theta,
            C_, N_, C_, P_, (size_t)C_ * N_, 0, (size_t)N_ * P_);
        gemm_kernel<true, false><<<grid, 256>>>(x, Wph, phi,
            C_, N_, C_, P_, (size_t)C_ * N_, 0, (size_t)N_ * P_);
        gemm_kernel<true, false><<<grid, 256>>>(x, Wg, g,
            C_, N_, C_, P_, (size_t)C_ * N_, 0, (size_t)N_ * P_);
    }

    // 2) scores: S[n,m] = sum_p theta[n,p] * phi[m,p]   (NT)
    {
        dim3 grid(N_ / 128, N_ / 128, B_);
        gemm_kernel<false, false><<<grid, 256>>>(theta, phi, S,
            P_, P_, P_, N_, (size_t)N_ * P_, (size_t)N_ * P_, (size_t)N_ * N_);
    }

    // 3) row softmax over S
    softmax_kernel<<<B_ * N_, 256>>>(S);

    // 4) PV: O[n,p] = sum_m S[n,m] * g[m,p]   (NN)
    {
        dim3 grid(P_ / 128, N_ / 128, B_);
        gemm_kernel<false, true><<<grid, 256>>>(S, g, O,
            N_, N_, P_, P_, (size_t)N_ * N_, (size_t)N_ * P_, (size_t)N_ * P_);
    }

    // 5) z: zp[c, b*N+n] = sum_p Wz[c,p] * O[(b*N+n), p]
    {
        dim3 grid((B_ * N_) / 128, C_ / 128, 1);
        gemm_kernel<false, false><<<grid, 256>>>(Wz, O, zp,
            P_, P_, P_, B_ * N_, 0, 0, 0);
    }

    // 6) BN statistics per channel
    bn_stats_kernel<<<C_, 256>>>(zp, gamma, beta, scale, shift);

    // 7) normalize + affine + residual
    {
        const int total4 = B_ * C_ * N_ / 4;
        finalize_kernel<<<(total4 + 255) / 256, 256>>>(zp, x, scale, shift, out);
    }
}

// round 4
// speedup vs baseline: 1.8243x; 1.7518x over previous
#include <cuda_runtime.h>
#include <cuda_bf16.h>
#include <math.h>
#include <stdint.h>

// Problem constants
#define B_ 8
#define C_ 512
#define N_ 2048
#define P_ 256

// ---------------- scratch (static device globals; no allocation) ----------------
__device__ __nv_bfloat16 d_xsA[(size_t)B_ * N_ * 3 * C_];   // x^T split, A-pattern [b][n][3C]
__device__ __nv_bfloat16 d_xsB[(size_t)B_ * N_ * 3 * C_];   // x^T split, B-pattern
__device__ __nv_bfloat16 d_WthS[P_ * 3 * C_];               // B-pattern
__device__ __nv_bfloat16 d_WphS[P_ * 3 * C_];               // B-pattern
__device__ __nv_bfloat16 d_WgS [P_ * 3 * C_];               // A-pattern
__device__ __nv_bfloat16 d_WzS [C_ * 3 * P_];               // A-pattern
__device__ __nv_bfloat16 d_thS[(size_t)B_ * N_ * 3 * P_];   // theta split A-pattern
__device__ __nv_bfloat16 d_phS[(size_t)B_ * N_ * 3 * P_];   // phi split B-pattern
__device__ __nv_bfloat16 d_gS [(size_t)B_ * P_ * 3 * N_];   // g^T split B-pattern [b][p][3N]
__device__ float         d_Sf [(size_t)B_ * N_ * N_];       // scores fp32
__device__ __nv_bfloat16 d_SsP[(size_t)B_ * N_ * 3 * N_];   // softmax probs split A-pattern
__device__ __nv_bfloat16 d_OS [(size_t)B_ * N_ * 3 * P_];   // attention out split B-pattern
__device__ float d_zp[(size_t)C_ * B_ * N_];                // z channel-major [C][B*N]
__device__ float d_scale[C_];
__device__ float d_shift[C_];

// ---------------- helpers ----------------
__device__ __forceinline__ uint32_t smem_to_u32(const void* p) {
    uint32_t a;
    asm("{ .reg .u64 t; cvta.to.shared.u64 t, %1; cvt.u32.u64 %0, t; }" : "=r"(a) : "l"(p));
    return a;
}
__device__ __forceinline__ void split2(float v, __nv_bfloat16& h, __nv_bfloat16& l) {
    h = __float2bfloat16(v);
    l = __float2bfloat16(v - __bfloat162float(h));
}
__device__ __forceinline__ uint32_t pack_bf16x2(float a, float b) {
    __nv_bfloat16 x = __float2bfloat16(a), y = __float2bfloat16(b);
    return (uint32_t)__bfloat16_as_ushort(x) | ((uint32_t)__bfloat16_as_ushort(y) << 16);
}

// ---------------- weight split (elementwise) ----------------
__global__ void split_mat_kernel(const float* __restrict__ in, __nv_bfloat16* __restrict__ out,
                                 int K, int patA, int total)
{
    int idx = blockIdx.x * blockDim.x + threadIdx.x;
    if (idx >= total) return;
    int r = idx / K, k = idx % K;
    __nv_bfloat16 h, l;
    split2(in[idx], h, l);
    __nv_bfloat16* o = out + (size_t)r * (3 * K);
    o[k] = h;
    if (patA) { o[K + k] = h; o[2 * K + k] = l; }
    else      { o[K + k] = l; o[2 * K + k] = h; }
}

// ---------------- x transpose + split ----------------
__global__ void xsplit_kernel(const float* __restrict__ x,
                              __nv_bfloat16* __restrict__ xsA,
                              __nv_bfloat16* __restrict__ xsB)
{
    __shared__ float t[32][33];
    const int b = blockIdx.z;
    const int n0 = blockIdx.x * 32, c0 = blockIdx.y * 32;
    const int tx = threadIdx.x, ty = threadIdx.y;
    const float* xb = x + (size_t)b * C_ * N_;
    t[ty][tx] = xb[(size_t)(c0 + ty) * N_ + n0 + tx];
    __syncthreads();
    float v = t[tx][ty];
    int n = n0 + ty, c = c0 + tx;
    __nv_bfloat16 h, l;
    split2(v, h, l);
    size_t row = ((size_t)b * N_ + n) * (size_t)(3 * C_);
    xsA[row + c] = h; xsA[row + C_ + c] = h; xsA[row + 2 * C_ + c] = l;
    xsB[row + c] = h; xsB[row + C_ + c] = l; xsB[row + 2 * C_ + c] = h;
}

// ---------------- mma.sync bf16 GEMM: C[i,j] = sum_k A[i,k]*B[j,k] ----------------
// Tile: 128x128, 8 warps (warp grid 4x2 -> warp tile 32x64), k-chunk 64.
// mode 0: fp32 out; mode 1: split A-pattern (hi@0,hi@J,lo@2J); mode 2: split B-pattern.
#define CH 64
#define PAD 72
#define BUF_ELEMS (128 * PAD)
#define GEMM_SMEM (4 * BUF_ELEMS * 2)

__global__ void __launch_bounds__(256, 2) gemm_mma_kernel(
    const __nv_bfloat16* __restrict__ A, int lda,
    const __nv_bfloat16* __restrict__ Bp, int ldb,
    void* __restrict__ Cout, int ldc, int Kp, int mode, int J,
    size_t sA, size_t sB, size_t sC)
{
    extern __shared__ __nv_bfloat16 sm[];
    // layout: [A0][B0][A1][B1], each 128*PAD bf16
    const uint32_t smu = smem_to_u32(sm);

    const int tid  = threadIdx.x;
    const int wid  = tid >> 5;
    const int lane = tid & 31;
    const int wm = wid & 3;        // warp m-block (32 rows)
    const int wn = wid >> 2;       // warp n-block (64 cols)
    const int bz = blockIdx.z;
    A  += (size_t)bz * sA;
    Bp += (size_t)bz * sB;
    const int m0 = blockIdx.y * 128;
    const int j0 = blockIdx.x * 128;

    float acc[2][8][4];
#pragma unroll
    for (int mt = 0; mt < 2; mt++)
#pragma unroll
        for (int nb = 0; nb < 8; nb++)
#pragma unroll
            for (int q = 0; q < 4; q++) acc[mt][nb][q] = 0.f;

    // per-thread cp.async coordinates: 1024 16B-units per operand tile
    const int r_  = tid >> 3;        // used with i*? -> recompute in loop
    (void)r_;

    auto issue_chunk = [&](int c, int buf) {
        const int k0 = c * CH;
        const uint32_t aBase = smu + (uint32_t)(2 * buf) * BUF_ELEMS * 2;
        const uint32_t bBase = smu + (uint32_t)(2 * buf + 1) * BUF_ELEMS * 2;
#pragma unroll
        for (int i = 0; i < 4; i++) {
            int lin = tid + i * 256;          // 0..1023
            int r  = lin >> 3;                // 0..127
            int c8 = lin & 7;                 // 0..7 (16B unit)
            const __nv_bfloat16* gA = A  + (size_t)(m0 + r) * lda + k0 + c8 * 8;
            const __nv_bfloat16* gB = Bp + (size_t)(j0 + r) * ldb + k0 + c8 * 8;
            uint32_t sa = aBase + (uint32_t)(r * PAD + c8 * 8) * 2;
            uint32_t sb = bBase + (uint32_t)(r * PAD + c8 * 8) * 2;
            asm volatile("cp.async.cg.shared.global [%0], [%1], 16;" :: "r"(sa), "l"(gA));
            asm volatile("cp.async.cg.shared.global [%0], [%1], 16;" :: "r"(sb), "l"(gB));
        }
        asm volatile("cp.async.commit_group;" ::: "memory");
    };

    const int NC = Kp / CH;
    issue_chunk(0, 0);

    for (int c = 0; c < NC; c++) {
        const int buf = c & 1;
        const bool more = (c + 1 < NC);
        if (more) issue_chunk(c + 1, buf ^ 1);

        if (more) asm volatile("cp.async.wait_group 1;" ::: "memory");
        else      asm volatile("cp.async.wait_group 0;" ::: "memory");
        __syncthreads();

        const uint32_t aBase = smu + (uint32_t)(2 * buf) * BUF_ELEMS * 2;
        const uint32_t bBase = smu + (uint32_t)(2 * buf + 1) * BUF_ELEMS * 2;

#pragma unroll
        for (int ks = 0; ks < 4; ks++) {
            const int k0 = ks * 16;
            const int lrow = lane & 15;
            const int kun  = lane >> 4;       // 0 or 1 -> k +0 / +8

            uint32_t af[2][4];
#pragma unroll
            for (int mt = 0; mt < 2; mt++) {
                uint32_t addr = aBase +
                    (uint32_t)((wm * 32 + mt * 16 + lrow) * PAD + k0 + kun * 8) * 2;
                asm volatile(
                    "ldmatrix.sync.aligned.m8n8.x4.shared.b16 {%0,%1,%2,%3}, [%4];"
                    : "=r"(af[mt][0]), "=r"(af[mt][1]), "=r"(af[mt][2]), "=r"(af[mt][3])
                    : "r"(addr));
            }
            uint32_t bf[8][2];
#pragma unroll
            for (int nb2 = 0; nb2 < 4; nb2++) {
                uint32_t r0, r1, r2, r3;
                uint32_t addr = bBase +
                    (uint32_t)((wn * 64 + nb2 * 16 + lrow) * PAD + k0 + kun * 8) * 2;
                asm volatile(
                    "ldmatrix.sync.aligned.m8n8.x4.shared.b16 {%0,%1,%2,%3}, [%4];"
                    : "=r"(r0), "=r"(r1), "=r"(r2), "=r"(r3)
                    : "r"(addr));
                bf[nb2 * 2][0] = r0; bf[nb2 * 2][1] = r2;
                bf[nb2 * 2 + 1][0] = r1; bf[nb2 * 2 + 1][1] = r3;
            }
#pragma unroll
            for (int mt = 0; mt < 2; mt++)
#pragma unroll
                for (int nb = 0; nb < 8; nb++) {
                    asm volatile(
                        "mma.sync.aligned.m16n8k16.row.col.f32.bf16.bf16.f32 "
                        "{%0,%1,%2,%3}, {%4,%5,%6,%7}, {%8,%9}, {%0,%1,%2,%3};"
                        : "+f"(acc[mt][nb][0]), "+f"(acc[mt][nb][1]),
                          "+f"(acc[mt][nb][2]), "+f"(acc[mt][nb][3])
                        : "r"(af[mt][0]), "r"(af[mt][1]), "r"(af[mt][2]), "r"(af[mt][3]),
                          "r"(bf[nb][0]), "r"(bf[nb][1]));
                }
        }
        __syncthreads();
    }

    // ---------------- epilogue ----------------
    const int g = lane >> 2;
    const int t = lane & 3;
#pragma unroll
    for (int mt = 0; mt < 2; mt++) {
        const int row0 = m0 + wm * 32 + mt * 16 + g;
        const int row1 = row0 + 8;
#pragma unroll
        for (int nb = 0; nb < 8; nb++) {
            const int col = j0 + wn * 64 + nb * 8 + t * 2;
            float d0 = acc[mt][nb][0], d1 = acc[mt][nb][1];
            float d2 = acc[mt][nb][2], d3 = acc[mt][nb][3];
            if (mode == 0) {
                float* base = (float*)Cout + (size_t)bz * sC;
                *(float2*)(base + (size_t)row0 * ldc + col) = make_float2(d0, d1);
                *(float2*)(base + (size_t)row1 * ldc + col) = make_float2(d2, d3);
            } else {
                __nv_bfloat16* base = (__nv_bfloat16*)Cout + (size_t)bz * sC;
                const int oh2 = (mode == 1) ? J : 2 * J;
                const int olo = (mode == 1) ? 2 * J : J;
                __nv_bfloat16 h0, l0, h1, l1;
                split2(d0, h0, l0); split2(d1, h1, l1);
                uint32_t hp = (uint32_t)__bfloat16_as_ushort(h0) | ((uint32_t)__bfloat16_as_ushort(h1) << 16);
                uint32_t lp = (uint32_t)__bfloat16_as_ushort(l0) | ((uint32_t)__bfloat16_as_ushort(l1) << 16);
                __nv_bfloat16* r0p = base + (size_t)row0 * ldc + col;
                *(uint32_t*)(r0p)       = hp;
                *(uint32_t*)(r0p + oh2) = hp;
                *(uint32_t*)(r0p + olo) = lp;
                split2(d2, h0, l0); split2(d3, h1, l1);
                hp = (uint32_t)__bfloat16_as_ushort(h0) | ((uint32_t)__bfloat16_as_ushort(h1) << 16);
                lp = (uint32_t)__bfloat16_as_ushort(l0) | ((uint32_t)__bfloat16_as_ushort(l1) << 16);
                __nv_bfloat16* r1p = base + (size_t)row1 * ldc + col;
                *(uint32_t*)(r1p)       = hp;
                *(uint32_t*)(r1p + oh2) = hp;
                *(uint32_t*)(r1p + olo) = lp;
            }
        }
    }
}

// ---------------- softmax + split(A-pattern) over rows of N_=2048 ----------------
__global__ void softmax_split_kernel(const float* __restrict__ S,
                                     __nv_bfloat16* __restrict__ Ssp)
{
    __shared__ float red[256];
    const size_t rowi = blockIdx.x;
    const float* row = S + rowi * N_;
    __nv_bfloat16* orow = Ssp + rowi * (size_t)(3 * N_);
    const int tid = threadIdx.x;

    float4 v0 = ((const float4*)row)[tid];
    float4 v1 = ((const float4*)row)[tid + 256];

    float m = fmaxf(fmaxf(fmaxf(v0.x, v0.y), fmaxf(v0.z, v0.w)),
                    fmaxf(fmaxf(v1.x, v1.y), fmaxf(v1.z, v1.w)));
    red[tid] = m;
    __syncthreads();
    for (int s = 128; s > 0; s >>= 1) {
        if (tid < s) red[tid] = fmaxf(red[tid], red[tid + s]);
        __syncthreads();
    }
    const float rowmax = red[0];
    __syncthreads();

    v0.x = expf(v0.x - rowmax); v0.y = expf(v0.y - rowmax);
    v0.z = expf(v0.z - rowmax); v0.w = expf(v0.w - rowmax);
    v1.x = expf(v1.x - rowmax); v1.y = expf(v1.y - rowmax);
    v1.z = expf(v1.z - rowmax); v1.w = expf(v1.w - rowmax);

    float sum = (v0.x + v0.y + v0.z + v0.w) + (v1.x + v1.y + v1.z + v1.w);
    red[tid] = sum;
    __syncthreads();
    for (int s = 128; s > 0; s >>= 1) {
        if (tid < s) red[tid] += red[tid + s];
        __syncthreads();
    }
    const float inv = 1.0f / red[0];

    v0.x *= inv; v0.y *= inv; v0.z *= inv; v0.w *= inv;
    v1.x *= inv; v1.y *= inv; v1.z *= inv; v1.w *= inv;

    float vv[8] = {v0.x, v0.y, v0.z, v0.w, v1.x, v1.y, v1.z, v1.w};
    int pos[2] = {tid * 4, 1024 + tid * 4};
#pragma unroll
    for (int gsel = 0; gsel < 2; gsel++) {
        __nv_bfloat16 h[4], l[4];
#pragma unroll
        for (int q = 0; q < 4; q++) split2(vv[gsel * 4 + q], h[q], l[q]);
        uint32_t h01 = (uint32_t)__bfloat16_as_ushort(h[0]) | ((uint32_t)__bfloat16_as_ushort(h[1]) << 16);
        uint32_t h23 = (uint32_t)__bfloat16_as_ushort(h[2]) | ((uint32_t)__bfloat16_as_ushort(h[3]) << 16);
        uint32_t l01 = (uint32_t)__bfloat16_as_ushort(l[0]) | ((uint32_t)__bfloat16_as_ushort(l[1]) << 16);
        uint32_t l23 = (uint32_t)__bfloat16_as_ushort(l[2]) | ((uint32_t)__bfloat16_as_ushort(l[3]) << 16);
        int p = pos[gsel];
        *(uint2*)(orow + p)          = make_uint2(h01, h23);
        *(uint2*)(orow + N_ + p)     = make_uint2(h01, h23);
        *(uint2*)(orow + 2 * N_ + p) = make_uint2(l01, l23);
    }
}

// ---------------- BN batch statistics per channel ----------------
__global__ void bn_stats_kernel(const float* __restrict__ zp,
                                const float* __restrict__ gamma,
                                const float* __restrict__ beta,
                                float* __restrict__ scale,
                                float* __restrict__ shift)
{
    __shared__ double rs[256];
    __shared__ double rs2[256];
    const int c = blockIdx.x;
    const int tid = threadIdx.x;
    const float* row = zp + (size_t)c * (B_ * N_);

    double s = 0.0, s2 = 0.0;
    const int n4 = (B_ * N_) / 4;
    for (int i = tid; i < n4; i += 256) {
        float4 v = ((const float4*)row)[i];
        s  += (double)v.x + (double)v.y + (double)v.z + (double)v.w;
        s2 += (double)v.x * v.x + (double)v.y * v.y +
              (double)v.z * v.z + (double)v.w * v.w;
    }
    rs[tid] = s; rs2[tid] = s2;
    __syncthreads();
    for (int st = 128; st > 0; st >>= 1) {
        if (tid < st) { rs[tid] += rs[tid + st]; rs2[tid] += rs2[tid + st]; }
        __syncthreads();
    }
    if (tid == 0) {
        const double M = (double)(B_ * N_);
        double mean = rs[0] / M;
        double var  = rs2[0] / M - mean * mean;
        double inv  = 1.0 / sqrt(var + 1e-5);
        double sc   = (double)gamma[c] * inv;
        scale[c] = (float)sc;
        shift[c] = (float)((double)beta[c] - mean * sc);
    }
}

// ---------------- finalize ----------------
__global__ void finalize_kernel(const float* __restrict__ zp,
                                const float* __restrict__ x,
                                const float* __restrict__ scale,
                                const float* __restrict__ shift,
                                float* __restrict__ out)
{
    const size_t idx4 = (size_t)blockIdx.x * blockDim.x + threadIdx.x;
    const size_t total4 = (size_t)B_ * C_ * N_ / 4;
    if (idx4 >= total4) return;
    const int nq = N_ / 4;
    int n4 = (int)(idx4 % nq);
    int c  = (int)((idx4 / nq) % C_);
    int b  = (int)(idx4 / ((size_t)nq * C_));

    float4 z = ((const float4*)zp)[(size_t)c * (B_ * N_ / 4) + (size_t)b * nq + n4];
    float4 xv = ((const float4*)x)[idx4];
    const float sc = scale[c], sh = shift[c];
    float4 o;
    o.x = z.x * sc + sh + xv.x;
    o.y = z.y * sc + sh + xv.y;
    o.z = z.z * sc + sh + xv.z;
    o.w = z.w * sc + sh + xv.w;
    ((float4*)out)[idx4] = o;
}

// ---------------- launch ----------------
template <typename T>
static T* sym_addr(const void* sym)
{
    void* p = nullptr;
    cudaGetSymbolAddress(&p, sym);
    return (T*)p;
}

extern "C" void kernel_launch(void* const* d_in, const int* in_sizes, int n_in,
                              void* d_out, int out_size)
{
    const float* x     = (const float*)d_in[0];
    const float* Wg    = (const float*)d_in[1];
    const float* Wth   = (const float*)d_in[2];
    const float* Wph   = (const float*)d_in[3];
    const float* Wz    = (const float*)d_in[4];
    const float* gamma = (const float*)d_in[5];
    const float* beta  = (const float*)d_in[6];
    float* out = (float*)d_out;

    __nv_bfloat16* xsA  = sym_addr<__nv_bfloat16>(d_xsA);
    __nv_bfloat16* xsB  = sym_addr<__nv_bfloat16>(d_xsB);
    __nv_bfloat16* WthS = sym_addr<__nv_bfloat16>(d_WthS);
    __nv_bfloat16* WphS = sym_addr<__nv_bfloat16>(d_WphS);
    __nv_bfloat16* WgS  = sym_addr<__nv_bfloat16>(d_WgS);
    __nv_bfloat16* WzS  = sym_addr<__nv_bfloat16>(d_WzS);
    __nv_bfloat16* thS  = sym_addr<__nv_bfloat16>(d_thS);
    __nv_bfloat16* phS  = sym_addr<__nv_bfloat16>(d_phS);
    __nv_bfloat16* gS   = sym_addr<__nv_bfloat16>(d_gS);
    float*         Sf   = sym_addr<float>(d_Sf);
    __nv_bfloat16* SsP  = sym_addr<__nv_bfloat16>(d_SsP);
    __nv_bfloat16* OS   = sym_addr<__nv_bfloat16>(d_OS);
    float* zp    = sym_addr<float>(d_zp);
    float* scale = sym_addr<float>(d_scale);
    float* shift = sym_addr<float>(d_shift);

    static bool attr_done = false;
    if (!attr_done) {
        cudaFuncSetAttribute(gemm_mma_kernel,
                             cudaFuncAttributeMaxDynamicSharedMemorySize, GEMM_SMEM);
        attr_done = true;
    }

    // --- splits ---
    split_mat_kernel<<<(P_ * C_ + 255) / 256, 256>>>(Wth, WthS, C_, 0, P_ * C_);
    split_mat_kernel<<<(P_ * C_ + 255) / 256, 256>>>(Wph, WphS, C_, 0, P_ * C_);
    split_mat_kernel<<<(P_ * C_ + 255) / 256, 256>>>(Wg,  WgS,  C_, 1, P_ * C_);
    split_mat_kernel<<<(C_ * P_ + 255) / 256, 256>>>(Wz,  WzS,  P_, 1, C_ * P_);
    xsplit_kernel<<<dim3(N_ / 32, C_ / 32, B_), dim3(32, 32)>>>(x, xsA, xsB);

    // --- theta [b][n][3P] splitA: A=xsA (K'=3C), B=WthS ---
    gemm_mma_kernel<<<dim3(P_ / 128, N_ / 128, B_), 256, GEMM_SMEM>>>(
        xsA, 3 * C_, WthS, 3 * C_, thS, 3 * P_, 3 * C_, 1, P_,
        (size_t)N_ * 3 * C_, 0, (size_t)N_ * 3 * P_);
    // --- phi [b][n][3P] splitB ---
    gemm_mma_kernel<<<dim3(P_ / 128, N_ / 128, B_), 256, GEMM_SMEM>>>(
        xsA, 3 * C_, WphS, 3 * C_, phS, 3 * P_, 3 * C_, 2, P_,
        (size_t)N_ * 3 * C_, 0, (size_t)N_ * 3 * P_);
    // --- g^T [b][p][3N] splitB: A=WgS (rows p), B=xsB (rows n) ---
    gemm_mma_kernel<<<dim3(N_ / 128, P_ / 128, B_), 256, GEMM_SMEM>>>(
        WgS, 3 * C_, xsB, 3 * C_, gS, 3 * N_, 3 * C_, 2, N_,
        0, (size_t)N_ * 3 * C_, (size_t)P_ * 3 * N_);
    // --- scores fp32: A=thS, B=phS, K'=3P ---
    gemm_mma_kernel<<<dim3(N_ / 128, N_ / 128, B_), 256, GEMM_SMEM>>>(
        thS, 3 * P_, phS, 3 * P_, Sf, N_, 3 * P_, 0, 0,
        (size_t)N_ * 3 * P_, (size_t)N_ * 3 * P_, (size_t)N_ * N_);
    // --- softmax + split ---
    softmax_split_kernel<<<B_ * N_, 256>>>(Sf, SsP);
    // --- PV: O [b][n][3P] splitB: A=SsP (K'=3N), B=gS ---
    gemm_mma_kernel<<<dim3(P_ / 128, N_ / 128, B_), 256, GEMM_SMEM>>>(
        SsP, 3 * N_, gS, 3 * N_, OS, 3 * P_, 3 * N_, 2, P_,
        (size_t)N_ * 3 * N_, (size_t)P_ * 3 * N_, (size_t)N_ * 3 * P_);
    // --- z fp32 [C][B*N]: A=WzS (rows c), B=OS (rows b*N+n), K'=3P ---
    gemm_mma_kernel<<<dim3((B_ * N_) / 128, C_ / 128, 1), 256, GEMM_SMEM>>>(
        WzS, 3 * P_, OS, 3 * P_, zp, B_ * N_, 3 * P_, 0, 0, 0, 0, 0);

    // --- BN + finalize ---
    bn_stats_kernel<<<C_, 256>>>(zp, gamma, beta, scale, shift);
    {
        const int total4 = B_ * C_ * N_ / 4;
        finalize_kernel<<<(total4 + 255) / 256, 256>>>(zp, x, scale, shift, out);
    }
}